// round 10
// baseline (speedup 1.0000x reference)
#include <cuda_runtime.h>
#include <cuda_fp16.h>
#include <cstdint>

// Problem constants
#define T_TOK 2048
#define HDIM  1024
#define FDIM  1024
#define NEXP  8
#define TOPK  2
#define NPAIR (T_TOK * TOPK)

// Tiling
#define BM 128
#define BK 32
#define NCH (HDIM / BK)          // 32 chunks
#define MAX_TILES 40
#define PAD_ROWS (MAX_TILES * BM)

// fp16 smem rows, stride 80 B (5 x 16B granules, gcd(5,8)=1 -> ldmatrix
// conflict-free). Unified 4-stage cp.async for A and B (both fp16 in gmem).
#define ROWB 80
#define TILEB (BM * ROWB)        // 10240 B
#define STAGEB (2 * TILEB)       // A + B per stage = 20480 B
#define SMEM_BYTES (4 * STAGEB)  // 81920 (2 CTAs/SM: 163.8KB <= 228KB)

#define GW_ELEMS (NEXP * 2 * FDIM * HDIM)   // 16777216
#define DW_ELEMS (NEXP * HDIM * FDIM)       // 8388608
#define GWCONV_BLKS 2048
#define DWCONV_Y 8               // gemm1 grid.y 16..23 -> 320 conv blocks

// Scratch (no allocations allowed)
__device__ int    d_sorted[PAD_ROWS];
__device__ int    d_tile_expert[MAX_TILES];
__device__ int    d_ntiles;
__device__ __half d_hs16[(size_t)T_TOK * HDIM];     // 4 MB
__device__ __half d_gw16[(size_t)GW_ELEMS];         // 32 MB
__device__ __half d_dw16[(size_t)DW_ELEMS];         // 16 MB
__device__ __half d_act[(size_t)PAD_ROWS * FDIM];   // 10 MB
__device__ float  d_y2[(size_t)NPAIR * HDIM];       // 16 MB

// ---------------------------------------------------------------------------
// Helpers
// ---------------------------------------------------------------------------
__device__ __forceinline__ uint32_t smem_u32(const void* p) {
    uint32_t a;
    asm("{ .reg .u64 t; cvta.to.shared.u64 t, %1; cvt.u32.u64 %0, t; }" : "=r"(a) : "l"(p));
    return a;
}
__device__ __forceinline__ uint32_t f2h2(float lo, float hi) {
    __half2 h = __floats2half2_rn(lo, hi);
    return *(uint32_t*)&h;
}
__device__ __forceinline__ void cpa16(uint32_t dst, const void* src) {
    asm volatile("cp.async.cg.shared.global [%0], [%1], 16;" :: "r"(dst), "l"(src));
}
#define CPA_COMMIT() asm volatile("cp.async.commit_group;" ::: "memory")
#define CPA_WAIT2()  asm volatile("cp.async.wait_group 2;" ::: "memory")

__device__ __forceinline__ void ldsm4(uint32_t* r, uint32_t addr) {
    asm volatile("ldmatrix.sync.aligned.m8n8.x4.shared.b16 {%0,%1,%2,%3}, [%4];"
                 : "=r"(r[0]), "=r"(r[1]), "=r"(r[2]), "=r"(r[3]) : "r"(addr));
}
__device__ __forceinline__ void mma16(float* d, const uint32_t* a, const uint32_t* b) {
    asm volatile(
        "mma.sync.aligned.m16n8k16.row.col.f32.f16.f16.f32 "
        "{%0,%1,%2,%3}, {%4,%5,%6,%7}, {%8,%9}, {%0,%1,%2,%3};"
        : "+f"(d[0]), "+f"(d[1]), "+f"(d[2]), "+f"(d[3])
        : "r"(a[0]), "r"(a[1]), "r"(a[2]), "r"(a[3]), "r"(b[0]), "r"(b[1]));
}
__device__ __forceinline__ uint4 cvt8(float4 a, float4 b) {
    uint4 o;
    o.x = f2h2(a.x, a.y); o.y = f2h2(a.z, a.w);
    o.z = f2h2(b.x, b.y); o.w = f2h2(b.z, b.w);
    return o;
}

// ---------------------------------------------------------------------------
// Setup: block 0 = routing; blocks 1..512 = hs conv; 513.. = gw conv
// ---------------------------------------------------------------------------
__global__ void setup_kernel(const float* __restrict__ hs, const int* __restrict__ ids,
                             const float* __restrict__ gw) {
    int tid = threadIdx.x;
    if (blockIdx.x == 0) {
        __shared__ int s_cnt[NEXP], s_start[NEXP], s_cur[NEXP];
        if (tid < NEXP) s_cnt[tid] = 0;
        __syncthreads();
        for (int p = tid; p < NPAIR; p += blockDim.x) atomicAdd(&s_cnt[ids[p]], 1);
        __syncthreads();
        if (tid == 0) {
            int acc = 0, nt = 0;
            for (int e = 0; e < NEXP; e++) {
                s_start[e] = acc;
                int te = (s_cnt[e] + BM - 1) / BM;
                for (int i = 0; i < te; i++) d_tile_expert[nt + i] = e;
                nt += te;
                acc += te * BM;
            }
            d_ntiles = nt;
        }
        __syncthreads();
        for (int i = tid; i < PAD_ROWS; i += blockDim.x) d_sorted[i] = -1;
        if (tid < NEXP) s_cur[tid] = s_start[tid];
        __syncthreads();
        for (int p = tid; p < NPAIR; p += blockDim.x) {
            int pos = atomicAdd(&s_cur[ids[p]], 1);
            d_sorted[pos] = p;
        }
    } else if (blockIdx.x <= 512) {
        // hs: 262144 uint4 outputs; 512 blocks x 256 thr x 2
        int j = (blockIdx.x - 1) * 512 + tid;
        const float4* s = (const float4*)hs;
        #pragma unroll
        for (int it = 0; it < 2; it++) {
            int i = j + it * 256;
            ((uint4*)d_hs16)[i] = cvt8(s[i * 2], s[i * 2 + 1]);
        }
    } else {
        // gw: 2097152 uint4 outputs; 2048 blocks x 256 thr x 4
        int j = (blockIdx.x - 513) * 256 + tid;
        const float4* s = (const float4*)gw;
        #pragma unroll
        for (int it = 0; it < 4; it++) {
            int i = j + it * (GWCONV_BLKS * 256);
            ((uint4*)d_gw16)[i] = cvt8(s[i * 2], s[i * 2 + 1]);
        }
    }
}

// ---------------------------------------------------------------------------
// GEMM1: act = silu(x@Wg^T)*(x@Wu^T). 128 thr (2x2 warps), warp 64m x 32f dual.
// Grid (40, 16 + DWCONV_Y): y<16 = GEMM work; y>=16 (scheduled last, fills the
// wave tail) = dw fp32->fp16 conversion for the next kernel.
// A and B both via unified 4-stage cp.async (fp16 gmem sources).
// ---------------------------------------------------------------------------
__global__ __launch_bounds__(128, 2)
void gemm1_kernel(const float* __restrict__ dw) {
    int tid = threadIdx.x;
    if (blockIdx.y >= 16) {
        // dw conversion: 1048576 uint4 outputs on 320 blocks x 128 thr
        int cb = (blockIdx.y - 16) * MAX_TILES + blockIdx.x;
        const float4* s = (const float4*)dw;
        for (int i = cb * 128 + tid; i < DW_ELEMS / 8; i += DWCONV_Y * MAX_TILES * 128)
            ((uint4*)d_dw16)[i] = cvt8(s[i * 2], s[i * 2 + 1]);
        return;
    }

    int tile = blockIdx.x;
    if (tile >= d_ntiles) return;
    int e  = d_tile_expert[tile];
    int f0 = blockIdx.y * 64;

    extern __shared__ __align__(16) char smem[];
    __shared__ int s_tok[BM];

    int lane = tid & 31, warp = tid >> 5;
    if (tid < BM) {
        int sp = d_sorted[tile * BM + tid];
        s_tok[tid] = (sp >= 0) ? (sp >> 1) : 0;
    }
    __syncthreads();

    const __half* gwe = d_gw16 + (size_t)e * (2 * FDIM) * HDIM;
    uint32_t sb = smem_u32(smem);

    // A: 512 x 16B slots (4/thread); B: 512 x 16B slots (4/thread)
    int ar[4], ac8[4], br[4], bc8[4];
    const __half* asrc[4];
    const __half* bsrc[4];
    #pragma unroll
    for (int i = 0; i < 4; i++) {
        int idx = tid + i * 128;
        ar[i] = idx >> 2; ac8[i] = idx & 3;
        asrc[i] = d_hs16 + (size_t)s_tok[ar[i]] * HDIM + ac8[i] * 8;
        br[i] = ar[i]; bc8[i] = ac8[i];
        int grow = (br[i] < 64) ? (f0 + br[i]) : (FDIM + f0 + (br[i] - 64));
        bsrc[i] = gwe + (size_t)grow * HDIM + bc8[i] * 8;
    }
    auto issue = [&](int c) {
        uint32_t st = sb + (c & 3) * STAGEB;
        #pragma unroll
        for (int i = 0; i < 4; i++)
            cpa16(st + ar[i] * ROWB + ac8[i] * 16, asrc[i] + c * BK);
        #pragma unroll
        for (int i = 0; i < 4; i++)
            cpa16(st + TILEB + br[i] * ROWB + bc8[i] * 16, bsrc[i] + c * BK);
    };

    int wm = warp & 1, wn = warp >> 1;
    int m_base = wm * 64, f_base = wn * 32;

    int g = lane >> 3;
    int a_row = (g & 1) * 8 + (lane & 7);
    int a_kb  = (g >> 1) * 16;
    int b_row = (g >> 1) * 8 + (lane & 7);
    int b_kb  = (g & 1) * 16;

    float accG[4][4][4], accU[4][4][4];
    #pragma unroll
    for (int mt = 0; mt < 4; mt++)
        #pragma unroll
        for (int nt = 0; nt < 4; nt++)
            #pragma unroll
            for (int i = 0; i < 4; i++) { accG[mt][nt][i] = 0.f; accU[mt][nt][i] = 0.f; }

    issue(0); CPA_COMMIT();
    issue(1); CPA_COMMIT();
    issue(2); CPA_COMMIT();

    for (int c = 0; c < NCH; c++) {
        CPA_WAIT2();
        __syncthreads();

        uint32_t Ab = sb + (c & 3) * STAGEB;
        uint32_t Bb = Ab + TILEB;

        #pragma unroll
        for (int kf = 0; kf < 2; kf++) {
            uint32_t af[4][4], bg[8], bu[8];
            #pragma unroll
            for (int mt = 0; mt < 4; mt++)
                ldsm4(af[mt], Ab + (m_base + mt * 16 + a_row) * ROWB + kf * 32 + a_kb);
            #pragma unroll
            for (int p = 0; p < 2; p++) {
                ldsm4(bg + p * 4, Bb + (f_base + p * 16 + b_row) * ROWB + kf * 32 + b_kb);
                ldsm4(bu + p * 4, Bb + (64 + f_base + p * 16 + b_row) * ROWB + kf * 32 + b_kb);
            }
            #pragma unroll
            for (int mt = 0; mt < 4; mt++)
                #pragma unroll
                for (int nt = 0; nt < 4; nt++) {
                    mma16(accG[mt][nt], af[mt], bg + nt * 2);
                    mma16(accU[mt][nt], af[mt], bu + nt * 2);
                }
        }
        __syncthreads();
        if (c + 3 < NCH) issue(c + 3);
        CPA_COMMIT();
    }

    #pragma unroll
    for (int mt = 0; mt < 4; mt++)
        #pragma unroll
        for (int nt = 0; nt < 4; nt++)
            #pragma unroll
            for (int half = 0; half < 2; half++) {
                int r  = m_base + mt * 16 + (lane >> 2) + half * 8;
                int cc = f0 + f_base + nt * 8 + (lane & 3) * 2;
                float g0 = accG[mt][nt][half * 2 + 0];
                float g1 = accG[mt][nt][half * 2 + 1];
                float u0 = accU[mt][nt][half * 2 + 0];
                float u1 = accU[mt][nt][half * 2 + 1];
                float a0 = g0 / (1.f + __expf(-g0)) * u0;
                float a1 = g1 / (1.f + __expf(-g1)) * u1;
                *(__half2*)&d_act[(size_t)(tile * BM + r) * FDIM + cc] =
                    __floats2half2_rn(a0, a1);
            }
}

// ---------------------------------------------------------------------------
// GEMM2: y2[pair] = tw[pair] * (act @ Wd[e]^T). 128 thr (2x2 warps),
// warp tile 64x64, BN=128. Grid (40,8). Unified 4-stage cp.async.
// ---------------------------------------------------------------------------
__global__ __launch_bounds__(128, 2)
void gemm2_kernel(const float* __restrict__ tw) {
    int tile = blockIdx.x;
    if (tile >= d_ntiles) return;
    int e  = d_tile_expert[tile];
    int h0 = blockIdx.y * 128;

    extern __shared__ __align__(16) char smem[];

    int tid = threadIdx.x, lane = tid & 31, warp = tid >> 5;
    const __half* dwe  = d_dw16 + (size_t)e * HDIM * FDIM;
    const __half* arow = d_act + (size_t)tile * BM * FDIM;
    uint32_t sb = smem_u32(smem);

    int ar[4], ac8[4];
    #pragma unroll
    for (int i = 0; i < 4; i++) {
        int idx = tid + i * 128;
        ar[i] = idx >> 2; ac8[i] = idx & 3;
    }
    auto issue = [&](int c) {
        uint32_t st = sb + (c & 3) * STAGEB;
        #pragma unroll
        for (int i = 0; i < 4; i++)
            cpa16(st + ar[i] * ROWB + ac8[i] * 16,
                  arow + (size_t)ar[i] * FDIM + c * BK + ac8[i] * 8);
        #pragma unroll
        for (int i = 0; i < 4; i++)
            cpa16(st + TILEB + ar[i] * ROWB + ac8[i] * 16,
                  dwe + (size_t)(h0 + ar[i]) * FDIM + c * BK + ac8[i] * 8);
    };

    int wm = warp & 1, wn = warp >> 1;
    int m_base = wm * 64, n_base = wn * 64;

    int g = lane >> 3;
    int a_row = (g & 1) * 8 + (lane & 7);
    int a_kb  = (g >> 1) * 16;
    int b_row = (g >> 1) * 8 + (lane & 7);
    int b_kb  = (g & 1) * 16;

    float acc[4][8][4];
    #pragma unroll
    for (int mt = 0; mt < 4; mt++)
        #pragma unroll
        for (int nt = 0; nt < 8; nt++)
            #pragma unroll
            for (int i = 0; i < 4; i++) acc[mt][nt][i] = 0.f;

    issue(0); CPA_COMMIT();
    issue(1); CPA_COMMIT();
    issue(2); CPA_COMMIT();

    for (int c = 0; c < NCH; c++) {
        CPA_WAIT2();
        __syncthreads();

        uint32_t Ab = sb + (c & 3) * STAGEB;
        uint32_t Bb = Ab + TILEB;

        #pragma unroll
        for (int kf = 0; kf < 2; kf++) {
            uint32_t af[4][4], bf[16];
            #pragma unroll
            for (int mt = 0; mt < 4; mt++)
                ldsm4(af[mt], Ab + (m_base + mt * 16 + a_row) * ROWB + kf * 32 + a_kb);
            #pragma unroll
            for (int p = 0; p < 4; p++)
                ldsm4(bf + p * 4, Bb + (n_base + p * 16 + b_row) * ROWB + kf * 32 + b_kb);
            #pragma unroll
            for (int mt = 0; mt < 4; mt++)
                #pragma unroll
                for (int nt = 0; nt < 8; nt++)
                    mma16(acc[mt][nt], af[mt], bf + nt * 2);
        }
        __syncthreads();
        if (c + 3 < NCH) issue(c + 3);
        CPA_COMMIT();
    }

    #pragma unroll
    for (int mt = 0; mt < 4; mt++)
        #pragma unroll
        for (int half = 0; half < 2; half++) {
            int r  = m_base + mt * 16 + (lane >> 2) + half * 8;
            int sp = d_sorted[tile * BM + r];
            if (sp < 0) continue;
            float wt = tw[sp];
            #pragma unroll
            for (int nt = 0; nt < 8; nt++) {
                int cc = h0 + n_base + nt * 8 + (lane & 3) * 2;
                float v0 = wt * acc[mt][nt][half * 2 + 0];
                float v1 = wt * acc[mt][nt][half * 2 + 1];
                *(float2*)&d_y2[(size_t)sp * HDIM + cc] = make_float2(v0, v1);
            }
        }
}

// ---------------------------------------------------------------------------
// Reduce: out[t] = y2[2t] + y2[2t+1]
// ---------------------------------------------------------------------------
__global__ void reduce_kernel(float* __restrict__ out) {
    int i = blockIdx.x * blockDim.x + threadIdx.x;
    int t = i >> 8, c4 = i & 255;
    const float4* y = (const float4*)d_y2;
    float4 a = y[(size_t)(t * 2) * 256 + c4];
    float4 b = y[(size_t)(t * 2 + 1) * 256 + c4];
    ((float4*)out)[i] = make_float4(a.x + b.x, a.y + b.y, a.z + b.z, a.w + b.w);
}

// ---------------------------------------------------------------------------
extern "C" void kernel_launch(void* const* d_in, const int* in_sizes, int n_in,
                              void* d_out, int out_size) {
    const float* hs  = (const float*)d_in[0];
    const float* tw  = (const float*)d_in[1];
    const int*   ids = (const int*)d_in[2];
    const float* gw  = (const float*)d_in[3];
    const float* dw  = (const float*)d_in[4];

    cudaFuncSetAttribute(gemm1_kernel, cudaFuncAttributeMaxDynamicSharedMemorySize, SMEM_BYTES);
    cudaFuncSetAttribute(gemm2_kernel, cudaFuncAttributeMaxDynamicSharedMemorySize, SMEM_BYTES);

    setup_kernel<<<1 + 512 + GWCONV_BLKS, 256>>>(hs, ids, gw);
    gemm1_kernel<<<dim3(MAX_TILES, 16 + DWCONV_Y), 128, SMEM_BYTES>>>(dw);
    gemm2_kernel<<<dim3(MAX_TILES, HDIM / 128), 128, SMEM_BYTES>>>(tw);
    reduce_kernel<<<(T_TOK * HDIM / 4) / 256, 256>>>((float*)d_out);
}

// round 11
// speedup vs baseline: 1.5631x; 1.5631x over previous
#include <cuda_runtime.h>
#include <cuda_fp16.h>
#include <cstdint>

// Problem constants
#define T_TOK 2048
#define HDIM  1024
#define FDIM  1024
#define NEXP  8
#define TOPK  2
#define NPAIR (T_TOK * TOPK)

// Tiling (R6 config)
#define BM 128
#define BK 32
#define NCH (HDIM / BK)          // 32 chunks
#define MAX_TILES 40
#define PAD_ROWS (MAX_TILES * BM)

// fp16 smem rows, stride 80 B (5 x 16B granules, gcd(5,8)=1 -> ldmatrix
// conflict-free). A: 4-stage cp.async. B: 2-stage reg-pipelined cvt.
#define ROWB 80
#define TILEB (BM * ROWB)        // 10240 B
#define A_STAGES 4
#define SMEM_BYTES (A_STAGES * TILEB + 2 * TILEB)   // 61440

// Scratch (no allocations allowed)
__device__ int    d_sorted[PAD_ROWS];
__device__ int    d_tile_expert[MAX_TILES];
__device__ int    d_ntiles;
__device__ __half d_hs16[(size_t)T_TOK * HDIM];     // 4 MB
__device__ __half d_act[(size_t)PAD_ROWS * FDIM];   // 10 MB

// ---------------------------------------------------------------------------
// Helpers
// ---------------------------------------------------------------------------
__device__ __forceinline__ uint32_t smem_u32(const void* p) {
    uint32_t a;
    asm("{ .reg .u64 t; cvta.to.shared.u64 t, %1; cvt.u32.u64 %0, t; }" : "=r"(a) : "l"(p));
    return a;
}
__device__ __forceinline__ uint32_t f2h2(float lo, float hi) {
    __half2 h = __floats2half2_rn(lo, hi);
    return *(uint32_t*)&h;
}
__device__ __forceinline__ void cpa16(uint32_t dst, const void* src) {
    asm volatile("cp.async.cg.shared.global [%0], [%1], 16;" :: "r"(dst), "l"(src));
}
#define CPA_COMMIT() asm volatile("cp.async.commit_group;" ::: "memory")
#define CPA_WAIT2()  asm volatile("cp.async.wait_group 2;" ::: "memory")

__device__ __forceinline__ void ldsm4(uint32_t* r, uint32_t addr) {
    asm volatile("ldmatrix.sync.aligned.m8n8.x4.shared.b16 {%0,%1,%2,%3}, [%4];"
                 : "=r"(r[0]), "=r"(r[1]), "=r"(r[2]), "=r"(r[3]) : "r"(addr));
}
__device__ __forceinline__ void mma16(float* d, const uint32_t* a, const uint32_t* b) {
    asm volatile(
        "mma.sync.aligned.m16n8k16.row.col.f32.f16.f16.f32 "
        "{%0,%1,%2,%3}, {%4,%5,%6,%7}, {%8,%9}, {%0,%1,%2,%3};"
        : "+f"(d[0]), "+f"(d[1]), "+f"(d[2]), "+f"(d[3])
        : "r"(a[0]), "r"(a[1]), "r"(a[2]), "r"(a[3]), "r"(b[0]), "r"(b[1]));
}

// ---------------------------------------------------------------------------
// Setup: block 0 = routing; blocks 1..512 = hs fp32 -> fp16 (2 uint4/thread)
// ---------------------------------------------------------------------------
__global__ void setup_kernel(const float* __restrict__ hs, const int* __restrict__ ids) {
    int tid = threadIdx.x;
    if (blockIdx.x == 0) {
        __shared__ int s_cnt[NEXP], s_start[NEXP], s_cur[NEXP];
        if (tid < NEXP) s_cnt[tid] = 0;
        __syncthreads();
        for (int p = tid; p < NPAIR; p += blockDim.x) atomicAdd(&s_cnt[ids[p]], 1);
        __syncthreads();
        if (tid == 0) {
            int acc = 0, nt = 0;
            for (int e = 0; e < NEXP; e++) {
                s_start[e] = acc;
                int te = (s_cnt[e] + BM - 1) / BM;
                for (int i = 0; i < te; i++) d_tile_expert[nt + i] = e;
                nt += te;
                acc += te * BM;
            }
            d_ntiles = nt;
        }
        __syncthreads();
        for (int i = tid; i < PAD_ROWS; i += blockDim.x) d_sorted[i] = -1;
        if (tid < NEXP) s_cur[tid] = s_start[tid];
        __syncthreads();
        for (int p = tid; p < NPAIR; p += blockDim.x) {
            int pos = atomicAdd(&s_cur[ids[p]], 1);
            d_sorted[pos] = p;
        }
    } else {
        // hs: 262144 uint4 outputs; 512 blocks x 256 thr x 2
        int j = (blockIdx.x - 1) * 512 + tid;
        const float4* s = (const float4*)hs;
        #pragma unroll
        for (int it = 0; it < 2; it++) {
            int i = j + it * 256;
            float4 a = s[i * 2], b = s[i * 2 + 1];
            uint4 o;
            o.x = f2h2(a.x, a.y); o.y = f2h2(a.z, a.w);
            o.z = f2h2(b.x, b.y); o.w = f2h2(b.z, b.w);
            ((uint4*)d_hs16)[i] = o;
        }
    }
}

// ---------------------------------------------------------------------------
// GEMM1 (R6 verbatim): act = silu(x@Wg^T)*(x@Wu^T).
// 128 thr (2x2 warps), warp tile 64m x 32f dual. Grid (40,16), 2 CTA/SM.
// ---------------------------------------------------------------------------
__global__ __launch_bounds__(128, 2)
void gemm1_kernel(const float* __restrict__ gw) {
    int tile = blockIdx.x;
    if (tile >= d_ntiles) return;
    int e  = d_tile_expert[tile];
    int f0 = blockIdx.y * 64;

    extern __shared__ __align__(16) char smem[];
    __shared__ int s_tok[BM];

    int tid = threadIdx.x, lane = tid & 31, warp = tid >> 5;
    if (tid < BM) {
        int sp = d_sorted[tile * BM + tid];
        s_tok[tid] = (sp >= 0) ? (sp >> 1) : 0;
    }
    __syncthreads();

    const float* gwe = gw + (size_t)e * (2 * FDIM) * HDIM;
    uint32_t sb = smem_u32(smem);
    uint32_t bbase0 = sb + A_STAGES * TILEB;

    int ar[4], ac8[4];
    const __half* asrc[4];
    #pragma unroll
    for (int i = 0; i < 4; i++) {
        int idx = tid + i * 128;
        ar[i] = idx >> 2; ac8[i] = idx & 3;
        asrc[i] = d_hs16 + (size_t)s_tok[ar[i]] * HDIM + ac8[i] * 8;
    }
    auto issueA = [&](int c) {
        uint32_t ab = sb + (c & 3) * TILEB;
        #pragma unroll
        for (int i = 0; i < 4; i++)
            cpa16(ab + ar[i] * ROWB + ac8[i] * 16, asrc[i] + c * BK);
    };

    int br[8], bc4[8];
    const float* bsrc[8];
    #pragma unroll
    for (int i = 0; i < 8; i++) {
        int idx = tid + i * 128;
        br[i] = idx >> 3; bc4[i] = idx & 7;
        int grow = (br[i] < 64) ? (f0 + br[i]) : (FDIM + f0 + (br[i] - 64));
        bsrc[i] = gwe + (size_t)grow * HDIM + bc4[i] * 4;
    }
    float4 bbuf[8];
    auto loadB = [&](int c) {
        #pragma unroll
        for (int i = 0; i < 8; i++) bbuf[i] = *(const float4*)(bsrc[i] + c * BK);
    };
    auto stsB = [&](int c) {
        char* bs = smem + A_STAGES * TILEB + (c & 1) * TILEB;
        #pragma unroll
        for (int i = 0; i < 8; i++)
            *(uint2*)(bs + br[i] * ROWB + bc4[i] * 8) =
                make_uint2(f2h2(bbuf[i].x, bbuf[i].y), f2h2(bbuf[i].z, bbuf[i].w));
    };

    int wm = warp & 1, wn = warp >> 1;
    int m_base = wm * 64, f_base = wn * 32;

    int g = lane >> 3;
    int a_row = (g & 1) * 8 + (lane & 7);
    int a_kb  = (g >> 1) * 16;
    int b_row = (g >> 1) * 8 + (lane & 7);
    int b_kb  = (g & 1) * 16;

    float accG[4][4][4], accU[4][4][4];
    #pragma unroll
    for (int mt = 0; mt < 4; mt++)
        #pragma unroll
        for (int nt = 0; nt < 4; nt++)
            #pragma unroll
            for (int i = 0; i < 4; i++) { accG[mt][nt][i] = 0.f; accU[mt][nt][i] = 0.f; }

    issueA(0); CPA_COMMIT();
    issueA(1); CPA_COMMIT();
    issueA(2); CPA_COMMIT();
    loadB(0); stsB(0); loadB(1);

    for (int c = 0; c < NCH; c++) {
        CPA_WAIT2();
        __syncthreads();

        uint32_t Ab = sb + (c & 3) * TILEB;
        uint32_t Bb = bbase0 + (c & 1) * TILEB;

        #pragma unroll
        for (int kf = 0; kf < 2; kf++) {
            uint32_t af[4][4], bg[8], bu[8];
            #pragma unroll
            for (int mt = 0; mt < 4; mt++)
                ldsm4(af[mt], Ab + (m_base + mt * 16 + a_row) * ROWB + kf * 32 + a_kb);
            #pragma unroll
            for (int p = 0; p < 2; p++) {
                ldsm4(bg + p * 4, Bb + (f_base + p * 16 + b_row) * ROWB + kf * 32 + b_kb);
                ldsm4(bu + p * 4, Bb + (64 + f_base + p * 16 + b_row) * ROWB + kf * 32 + b_kb);
            }
            #pragma unroll
            for (int mt = 0; mt < 4; mt++)
                #pragma unroll
                for (int nt = 0; nt < 4; nt++) {
                    mma16(accG[mt][nt], af[mt], bg + nt * 2);
                    mma16(accU[mt][nt], af[mt], bu + nt * 2);
                }
        }
        if (c + 1 < NCH) stsB(c + 1);
        if (c + 2 < NCH) loadB(c + 2);
        if (c + 3 < NCH) issueA(c + 3);
        CPA_COMMIT();
    }

    #pragma unroll
    for (int mt = 0; mt < 4; mt++)
        #pragma unroll
        for (int nt = 0; nt < 4; nt++)
            #pragma unroll
            for (int half = 0; half < 2; half++) {
                int r  = m_base + mt * 16 + (lane >> 2) + half * 8;
                int cc = f0 + f_base + nt * 8 + (lane & 3) * 2;
                float g0 = accG[mt][nt][half * 2 + 0];
                float g1 = accG[mt][nt][half * 2 + 1];
                float u0 = accU[mt][nt][half * 2 + 0];
                float u1 = accU[mt][nt][half * 2 + 1];
                float a0 = g0 / (1.f + __expf(-g0)) * u0;
                float a1 = g1 / (1.f + __expf(-g1)) * u1;
                *(__half2*)&d_act[(size_t)(tile * BM + r) * FDIM + cc] =
                    __floats2half2_rn(a0, a1);
            }
}

// ---------------------------------------------------------------------------
// GEMM2 (R6 mainloop): out[t] += tw[pair] * (act @ Wd[e]^T).
// 128 thr (2x2 warps), warp tile 64x64, BN=128. Grid (40,8), 2 CTA/SM.
// Epilogue: 2 commutative fp32 atomicAdds per output -> deterministic.
// ---------------------------------------------------------------------------
__global__ __launch_bounds__(128, 2)
void gemm2_kernel(const float* __restrict__ dw, const float* __restrict__ tw,
                  float* __restrict__ out) {
    int tile = blockIdx.x;
    if (tile >= d_ntiles) return;
    int e  = d_tile_expert[tile];
    int h0 = blockIdx.y * 128;

    extern __shared__ __align__(16) char smem[];

    int tid = threadIdx.x, lane = tid & 31, warp = tid >> 5;
    const float*  dwe  = dw + (size_t)e * HDIM * FDIM;
    const __half* arow = d_act + (size_t)tile * BM * FDIM;
    uint32_t sb = smem_u32(smem);
    uint32_t bbase0 = sb + A_STAGES * TILEB;

    int ar[4], ac8[4];
    #pragma unroll
    for (int i = 0; i < 4; i++) {
        int idx = tid + i * 128;
        ar[i] = idx >> 2; ac8[i] = idx & 3;
    }
    auto issueA = [&](int c) {
        uint32_t ab = sb + (c & 3) * TILEB;
        #pragma unroll
        for (int i = 0; i < 4; i++)
            cpa16(ab + ar[i] * ROWB + ac8[i] * 16,
                  arow + (size_t)ar[i] * FDIM + c * BK + ac8[i] * 8);
    };

    int br[8], bc4[8];
    #pragma unroll
    for (int i = 0; i < 8; i++) {
        int idx = tid + i * 128;
        br[i] = idx >> 3; bc4[i] = idx & 7;
    }
    float4 bbuf[8];
    auto loadB = [&](int c) {
        #pragma unroll
        for (int i = 0; i < 8; i++)
            bbuf[i] = *(const float4*)(dwe + (size_t)(h0 + br[i]) * FDIM + c * BK + bc4[i] * 4);
    };
    auto stsB = [&](int c) {
        char* bs = smem + A_STAGES * TILEB + (c & 1) * TILEB;
        #pragma unroll
        for (int i = 0; i < 8; i++)
            *(uint2*)(bs + br[i] * ROWB + bc4[i] * 8) =
                make_uint2(f2h2(bbuf[i].x, bbuf[i].y), f2h2(bbuf[i].z, bbuf[i].w));
    };

    int wm = warp & 1, wn = warp >> 1;
    int m_base = wm * 64, n_base = wn * 64;

    int g = lane >> 3;
    int a_row = (g & 1) * 8 + (lane & 7);
    int a_kb  = (g >> 1) * 16;
    int b_row = (g >> 1) * 8 + (lane & 7);
    int b_kb  = (g & 1) * 16;

    float acc[4][8][4];
    #pragma unroll
    for (int mt = 0; mt < 4; mt++)
        #pragma unroll
        for (int nt = 0; nt < 8; nt++)
            #pragma unroll
            for (int i = 0; i < 4; i++) acc[mt][nt][i] = 0.f;

    issueA(0); CPA_COMMIT();
    issueA(1); CPA_COMMIT();
    issueA(2); CPA_COMMIT();
    loadB(0); stsB(0); loadB(1);

    for (int c = 0; c < NCH; c++) {
        CPA_WAIT2();
        __syncthreads();

        uint32_t Ab = sb + (c & 3) * TILEB;
        uint32_t Bb = bbase0 + (c & 1) * TILEB;

        #pragma unroll
        for (int kf = 0; kf < 2; kf++) {
            uint32_t af[4][4], bf[16];
            #pragma unroll
            for (int mt = 0; mt < 4; mt++)
                ldsm4(af[mt], Ab + (m_base + mt * 16 + a_row) * ROWB + kf * 32 + a_kb);
            #pragma unroll
            for (int p = 0; p < 4; p++)
                ldsm4(bf + p * 4, Bb + (n_base + p * 16 + b_row) * ROWB + kf * 32 + b_kb);
            #pragma unroll
            for (int mt = 0; mt < 4; mt++)
                #pragma unroll
                for (int nt = 0; nt < 8; nt++)
                    mma16(acc[mt][nt], af[mt], bf + nt * 2);
        }
        if (c + 1 < NCH) stsB(c + 1);
        if (c + 2 < NCH) loadB(c + 2);
        if (c + 3 < NCH) issueA(c + 3);
        CPA_COMMIT();
    }

    // Epilogue: atomic accumulate w*acc into out (2 commutative fp32 adds per
    // element across the grid -> bitwise deterministic).
    #pragma unroll
    for (int mt = 0; mt < 4; mt++)
        #pragma unroll
        for (int half = 0; half < 2; half++) {
            int r  = m_base + mt * 16 + (lane >> 2) + half * 8;
            int sp = d_sorted[tile * BM + r];
            if (sp < 0) continue;
            float wt = tw[sp];
            float* orow = out + (size_t)(sp >> 1) * HDIM;
            #pragma unroll
            for (int nt = 0; nt < 8; nt++) {
                int cc = h0 + n_base + nt * 8 + (lane & 3) * 2;
                atomicAdd(&orow[cc],     wt * acc[mt][nt][half * 2 + 0]);
                atomicAdd(&orow[cc + 1], wt * acc[mt][nt][half * 2 + 1]);
            }
        }
}

// ---------------------------------------------------------------------------
extern "C" void kernel_launch(void* const* d_in, const int* in_sizes, int n_in,
                              void* d_out, int out_size) {
    const float* hs  = (const float*)d_in[0];
    const float* tw  = (const float*)d_in[1];
    const int*   ids = (const int*)d_in[2];
    const float* gw  = (const float*)d_in[3];
    const float* dw  = (const float*)d_in[4];

    cudaFuncSetAttribute(gemm1_kernel, cudaFuncAttributeMaxDynamicSharedMemorySize, SMEM_BYTES);
    cudaFuncSetAttribute(gemm2_kernel, cudaFuncAttributeMaxDynamicSharedMemorySize, SMEM_BYTES);

    cudaMemsetAsync(d_out, 0, (size_t)out_size * sizeof(float));
    setup_kernel<<<1 + 512, 256>>>(hs, ids);
    gemm1_kernel<<<dim3(MAX_TILES, FDIM / 64), 128, SMEM_BYTES>>>(gw);
    gemm2_kernel<<<dim3(MAX_TILES, HDIM / 128), 128, SMEM_BYTES>>>(dw, tw, (float*)d_out);
}

// round 13
// speedup vs baseline: 1.5738x; 1.0069x over previous
#include <cuda_runtime.h>
#include <cuda_fp16.h>
#include <cstdint>

// Problem constants
#define T_TOK 2048
#define HDIM  1024
#define FDIM  1024
#define NEXP  8
#define TOPK  2
#define NPAIR (T_TOK * TOPK)

// Tiling (R6/R11 config)
#define BM 128
#define BK 32
#define NCH (HDIM / BK)          // 32 chunks
#define MAX_TILES 40
#define PAD_ROWS (MAX_TILES * BM)

// fp16 smem rows, stride 80 B (5 x 16B granules, gcd(5,8)=1 -> ldmatrix
// conflict-free). A: 4-stage cp.async. B: 2-stage reg-pipelined cvt.
#define ROWB 80
#define TILEB (BM * ROWB)        // 10240 B
#define A_STAGES 4
#define SMEM_BYTES (A_STAGES * TILEB + 2 * TILEB)   // 61440

// Scratch (no allocations allowed)
__device__ int    d_sorted[PAD_ROWS];
__device__ int    d_tile_expert[MAX_TILES];
__device__ int    d_ntiles;
__device__ __half d_hs16[(size_t)T_TOK * HDIM];     // 4 MB
__device__ __half d_act[(size_t)PAD_ROWS * FDIM];   // 10 MB

// ---------------------------------------------------------------------------
// Helpers
// ---------------------------------------------------------------------------
__device__ __forceinline__ uint32_t smem_u32(const void* p) {
    uint32_t a;
    asm("{ .reg .u64 t; cvta.to.shared.u64 t, %1; cvt.u32.u64 %0, t; }" : "=r"(a) : "l"(p));
    return a;
}
__device__ __forceinline__ uint32_t f2h2(float lo, float hi) {
    __half2 h = __floats2half2_rn(lo, hi);
    return *(uint32_t*)&h;
}
__device__ __forceinline__ void cpa16(uint32_t dst, const void* src) {
    asm volatile("cp.async.cg.shared.global [%0], [%1], 16;" :: "r"(dst), "l"(src));
}
#define CPA_COMMIT() asm volatile("cp.async.commit_group;" ::: "memory")
#define CPA_WAIT2()  asm volatile("cp.async.wait_group 2;" ::: "memory")

__device__ __forceinline__ void ldsm4(uint32_t* r, uint32_t addr) {
    asm volatile("ldmatrix.sync.aligned.m8n8.x4.shared.b16 {%0,%1,%2,%3}, [%4];"
                 : "=r"(r[0]), "=r"(r[1]), "=r"(r[2]), "=r"(r[3]) : "r"(addr));
}
__device__ __forceinline__ void mma16(float* d, const uint32_t* a, const uint32_t* b) {
    asm volatile(
        "mma.sync.aligned.m16n8k16.row.col.f32.f16.f16.f32 "
        "{%0,%1,%2,%3}, {%4,%5,%6,%7}, {%8,%9}, {%0,%1,%2,%3};"
        : "+f"(d[0]), "+f"(d[1]), "+f"(d[2]), "+f"(d[3])
        : "r"(a[0]), "r"(a[1]), "r"(a[2]), "r"(a[3]), "r"(b[0]), "r"(b[1]));
}
// PDL intrinsics
__device__ __forceinline__ void pdl_trigger() {
    asm volatile("griddepcontrol.launch_dependents;" ::: "memory");
}
__device__ __forceinline__ void pdl_wait() {
    asm volatile("griddepcontrol.wait;" ::: "memory");
}

// ---------------------------------------------------------------------------
// Setup: block 0 = routing; blocks 1..512 = hs fp32->fp16 + d_out zeroing.
// pdl_trigger at END of each block -> dependents see all writes complete.
// ---------------------------------------------------------------------------
__global__ void setup_kernel(const float* __restrict__ hs, const int* __restrict__ ids,
                             float* __restrict__ out) {
    int tid = threadIdx.x;
    if (blockIdx.x == 0) {
        __shared__ int s_cnt[NEXP], s_start[NEXP], s_cur[NEXP];
        if (tid < NEXP) s_cnt[tid] = 0;
        __syncthreads();
        for (int p = tid; p < NPAIR; p += blockDim.x) atomicAdd(&s_cnt[ids[p]], 1);
        __syncthreads();
        if (tid == 0) {
            int acc = 0, nt = 0;
            for (int e = 0; e < NEXP; e++) {
                s_start[e] = acc;
                int te = (s_cnt[e] + BM - 1) / BM;
                for (int i = 0; i < te; i++) d_tile_expert[nt + i] = e;
                nt += te;
                acc += te * BM;
            }
            d_ntiles = nt;
        }
        __syncthreads();
        for (int i = tid; i < PAD_ROWS; i += blockDim.x) d_sorted[i] = -1;
        if (tid < NEXP) s_cur[tid] = s_start[tid];
        __syncthreads();
        for (int p = tid; p < NPAIR; p += blockDim.x) {
            int pos = atomicAdd(&s_cur[ids[p]], 1);
            d_sorted[pos] = p;
        }
        __syncthreads();
    } else {
        // hs conv: 262144 uint4; 512 blocks x 256 thr x 2
        int j = (blockIdx.x - 1) * 512 + tid;
        const float4* s = (const float4*)hs;
        #pragma unroll
        for (int it = 0; it < 2; it++) {
            int i = j + it * 256;
            float4 a = s[i * 2], b = s[i * 2 + 1];
            uint4 o;
            o.x = f2h2(a.x, a.y); o.y = f2h2(a.z, a.w);
            o.z = f2h2(b.x, b.y); o.w = f2h2(b.z, b.w);
            ((uint4*)d_hs16)[i] = o;
        }
        // d_out zero: 524288 uint4; 512 blocks x 256 thr x 4
        uint4 z = make_uint4(0, 0, 0, 0);
        int base = (blockIdx.x - 1) * 1024 + tid;
        #pragma unroll
        for (int it = 0; it < 4; it++)
            ((uint4*)out)[base + it * 256] = z;
    }
    pdl_trigger();   // all of this block's work done
}

// ---------------------------------------------------------------------------
// GEMM1 (R11 body): act = silu(x@Wg^T)*(x@Wu^T). Grid (40,16), 2 CTA/SM.
// Trigger at TOP (lets gemm2 launch during our last wave); wait immediately
// (setup triggered at end, so this is cheap and fences d_sorted/d_hs16).
// ---------------------------------------------------------------------------
__global__ __launch_bounds__(128, 2)
void gemm1_kernel(const float* __restrict__ gw) {
    pdl_trigger();
    pdl_wait();      // setup grid complete; its writes visible

    int tile = blockIdx.x;
    if (tile >= d_ntiles) return;
    int e  = d_tile_expert[tile];
    int f0 = blockIdx.y * 64;

    extern __shared__ __align__(16) char smem[];
    __shared__ int s_tok[BM];

    int tid = threadIdx.x, lane = tid & 31, warp = tid >> 5;
    if (tid < BM) {
        int sp = d_sorted[tile * BM + tid];
        s_tok[tid] = (sp >= 0) ? (sp >> 1) : 0;
    }
    __syncthreads();

    const float* gwe = gw + (size_t)e * (2 * FDIM) * HDIM;
    uint32_t sb = smem_u32(smem);
    uint32_t bbase0 = sb + A_STAGES * TILEB;

    int ar[4], ac8[4];
    const __half* asrc[4];
    #pragma unroll
    for (int i = 0; i < 4; i++) {
        int idx = tid + i * 128;
        ar[i] = idx >> 2; ac8[i] = idx & 3;
        asrc[i] = d_hs16 + (size_t)s_tok[ar[i]] * HDIM + ac8[i] * 8;
    }
    auto issueA = [&](int c) {
        uint32_t ab = sb + (c & 3) * TILEB;
        #pragma unroll
        for (int i = 0; i < 4; i++)
            cpa16(ab + ar[i] * ROWB + ac8[i] * 16, asrc[i] + c * BK);
    };

    int br[8], bc4[8];
    const float* bsrc[8];
    #pragma unroll
    for (int i = 0; i < 8; i++) {
        int idx = tid + i * 128;
        br[i] = idx >> 3; bc4[i] = idx & 7;
        int grow = (br[i] < 64) ? (f0 + br[i]) : (FDIM + f0 + (br[i] - 64));
        bsrc[i] = gwe + (size_t)grow * HDIM + bc4[i] * 4;
    }
    float4 bbuf[8];
    auto loadB = [&](int c) {
        #pragma unroll
        for (int i = 0; i < 8; i++) bbuf[i] = *(const float4*)(bsrc[i] + c * BK);
    };
    auto stsB = [&](int c) {
        char* bs = smem + A_STAGES * TILEB + (c & 1) * TILEB;
        #pragma unroll
        for (int i = 0; i < 8; i++)
            *(uint2*)(bs + br[i] * ROWB + bc4[i] * 8) =
                make_uint2(f2h2(bbuf[i].x, bbuf[i].y), f2h2(bbuf[i].z, bbuf[i].w));
    };

    int wm = warp & 1, wn = warp >> 1;
    int m_base = wm * 64, f_base = wn * 32;

    int g = lane >> 3;
    int a_row = (g & 1) * 8 + (lane & 7);
    int a_kb  = (g >> 1) * 16;
    int b_row = (g >> 1) * 8 + (lane & 7);
    int b_kb  = (g & 1) * 16;

    float accG[4][4][4], accU[4][4][4];
    #pragma unroll
    for (int mt = 0; mt < 4; mt++)
        #pragma unroll
        for (int nt = 0; nt < 4; nt++)
            #pragma unroll
            for (int i = 0; i < 4; i++) { accG[mt][nt][i] = 0.f; accU[mt][nt][i] = 0.f; }

    issueA(0); CPA_COMMIT();
    issueA(1); CPA_COMMIT();
    issueA(2); CPA_COMMIT();
    loadB(0); stsB(0); loadB(1);

    for (int c = 0; c < NCH; c++) {
        CPA_WAIT2();
        __syncthreads();

        uint32_t Ab = sb + (c & 3) * TILEB;
        uint32_t Bb = bbase0 + (c & 1) * TILEB;

        #pragma unroll
        for (int kf = 0; kf < 2; kf++) {
            uint32_t af[4][4], bg[8], bu[8];
            #pragma unroll
            for (int mt = 0; mt < 4; mt++)
                ldsm4(af[mt], Ab + (m_base + mt * 16 + a_row) * ROWB + kf * 32 + a_kb);
            #pragma unroll
            for (int p = 0; p < 2; p++) {
                ldsm4(bg + p * 4, Bb + (f_base + p * 16 + b_row) * ROWB + kf * 32 + b_kb);
                ldsm4(bu + p * 4, Bb + (64 + f_base + p * 16 + b_row) * ROWB + kf * 32 + b_kb);
            }
            #pragma unroll
            for (int mt = 0; mt < 4; mt++)
                #pragma unroll
                for (int nt = 0; nt < 4; nt++) {
                    mma16(accG[mt][nt], af[mt], bg + nt * 2);
                    mma16(accU[mt][nt], af[mt], bu + nt * 2);
                }
        }
        if (c + 1 < NCH) stsB(c + 1);
        if (c + 2 < NCH) loadB(c + 2);
        if (c + 3 < NCH) issueA(c + 3);
        CPA_COMMIT();
    }

    #pragma unroll
    for (int mt = 0; mt < 4; mt++)
        #pragma unroll
        for (int nt = 0; nt < 4; nt++)
            #pragma unroll
            for (int half = 0; half < 2; half++) {
                int r  = m_base + mt * 16 + (lane >> 2) + half * 8;
                int cc = f0 + f_base + nt * 8 + (lane & 3) * 2;
                float g0 = accG[mt][nt][half * 2 + 0];
                float g1 = accG[mt][nt][half * 2 + 1];
                float u0 = accU[mt][nt][half * 2 + 0];
                float u1 = accU[mt][nt][half * 2 + 1];
                float a0 = g0 / (1.f + __expf(-g0)) * u0;
                float a1 = g1 / (1.f + __expf(-g1)) * u1;
                *(__half2*)&d_act[(size_t)(tile * BM + r) * FDIM + cc] =
                    __floats2half2_rn(a0, a1);
            }
}

// ---------------------------------------------------------------------------
// GEMM2 (R11 body): out[t] += tw[pair] * (act @ Wd[e]^T). Grid (40,8).
// Launches during gemm1's last wave. Preamble touches only setup outputs
// (complete before gemm1 launched) + dw input; pdl_wait before d_act.
// ---------------------------------------------------------------------------
__global__ __launch_bounds__(128, 2)
void gemm2_kernel(const float* __restrict__ dw, const float* __restrict__ tw,
                  float* __restrict__ out) {
    pdl_trigger();
    int tile = blockIdx.x;
    if (tile >= d_ntiles) { pdl_wait(); return; }
    int e  = d_tile_expert[tile];
    int h0 = blockIdx.y * 128;

    extern __shared__ __align__(16) char smem[];

    int tid = threadIdx.x, lane = tid & 31, warp = tid >> 5;
    const float* dwe = dw + (size_t)e * HDIM * FDIM;
    uint32_t sb = smem_u32(smem);
    uint32_t bbase0 = sb + A_STAGES * TILEB;

    // B pointers + stage-0/1 prefetch (dw input + setup outputs only)
    int br[8], bc4[8];
    #pragma unroll
    for (int i = 0; i < 8; i++) {
        int idx = tid + i * 128;
        br[i] = idx >> 3; bc4[i] = idx & 7;
    }
    float4 bbuf[8];
    auto loadB = [&](int c) {
        #pragma unroll
        for (int i = 0; i < 8; i++)
            bbuf[i] = *(const float4*)(dwe + (size_t)(h0 + br[i]) * FDIM + c * BK + bc4[i] * 4);
    };
    auto stsB = [&](int c) {
        char* bs = smem + A_STAGES * TILEB + (c & 1) * TILEB;
        #pragma unroll
        for (int i = 0; i < 8; i++)
            *(uint2*)(bs + br[i] * ROWB + bc4[i] * 8) =
                make_uint2(f2h2(bbuf[i].x, bbuf[i].y), f2h2(bbuf[i].z, bbuf[i].w));
    };
    loadB(0); stsB(0); loadB(1);
    __syncthreads();

    pdl_wait();      // gemm1 grid complete: d_act readable

    const __half* arow = d_act + (size_t)tile * BM * FDIM;
    int ar[4], ac8[4];
    #pragma unroll
    for (int i = 0; i < 4; i++) {
        int idx = tid + i * 128;
        ar[i] = idx >> 2; ac8[i] = idx & 3;
    }
    auto issueA = [&](int c) {
        uint32_t ab = sb + (c & 3) * TILEB;
        #pragma unroll
        for (int i = 0; i < 4; i++)
            cpa16(ab + ar[i] * ROWB + ac8[i] * 16,
                  arow + (size_t)ar[i] * FDIM + c * BK + ac8[i] * 8);
    };

    int wm = warp & 1, wn = warp >> 1;
    int m_base = wm * 64, n_base = wn * 64;

    int g = lane >> 3;
    int a_row = (g & 1) * 8 + (lane & 7);
    int a_kb  = (g >> 1) * 16;
    int b_row = (g >> 1) * 8 + (lane & 7);
    int b_kb  = (g & 1) * 16;

    float acc[4][8][4];
    #pragma unroll
    for (int mt = 0; mt < 4; mt++)
        #pragma unroll
        for (int nt = 0; nt < 8; nt++)
            #pragma unroll
            for (int i = 0; i < 4; i++) acc[mt][nt][i] = 0.f;

    issueA(0); CPA_COMMIT();
    issueA(1); CPA_COMMIT();
    issueA(2); CPA_COMMIT();

    for (int c = 0; c < NCH; c++) {
        CPA_WAIT2();
        __syncthreads();

        uint32_t Ab = sb + (c & 3) * TILEB;
        uint32_t Bb = bbase0 + (c & 1) * TILEB;

        #pragma unroll
        for (int kf = 0; kf < 2; kf++) {
            uint32_t af[4][4], bf[16];
            #pragma unroll
            for (int mt = 0; mt < 4; mt++)
                ldsm4(af[mt], Ab + (m_base + mt * 16 + a_row) * ROWB + kf * 32 + a_kb);
            #pragma unroll
            for (int p = 0; p < 4; p++)
                ldsm4(bf + p * 4, Bb + (n_base + p * 16 + b_row) * ROWB + kf * 32 + b_kb);
            #pragma unroll
            for (int mt = 0; mt < 4; mt++)
                #pragma unroll
                for (int nt = 0; nt < 8; nt++)
                    mma16(acc[mt][nt], af[mt], bf + nt * 2);
        }
        if (c + 1 < NCH) stsB(c + 1);
        if (c + 2 < NCH) loadB(c + 2);
        if (c + 3 < NCH) issueA(c + 3);
        CPA_COMMIT();
    }

    // Epilogue: 2 commutative fp32 atomicAdds per output -> deterministic.
    #pragma unroll
    for (int mt = 0; mt < 4; mt++)
        #pragma unroll
        for (int half = 0; half < 2; half++) {
            int r  = m_base + mt * 16 + (lane >> 2) + half * 8;
            int sp = d_sorted[tile * BM + r];
            if (sp < 0) continue;
            float wt = tw[sp];
            float* orow = out + (size_t)(sp >> 1) * HDIM;
            #pragma unroll
            for (int nt = 0; nt < 8; nt++) {
                int cc = h0 + n_base + nt * 8 + (lane & 3) * 2;
                atomicAdd(&orow[cc],     wt * acc[mt][nt][half * 2 + 0]);
                atomicAdd(&orow[cc + 1], wt * acc[mt][nt][half * 2 + 1]);
            }
        }
}

// ---------------------------------------------------------------------------
extern "C" void kernel_launch(void* const* d_in, const int* in_sizes, int n_in,
                              void* d_out, int out_size) {
    const float* hs  = (const float*)d_in[0];
    const float* tw  = (const float*)d_in[1];
    const int*   ids = (const int*)d_in[2];
    const float* gw  = (const float*)d_in[3];
    const float* dw  = (const float*)d_in[4];
    float* out = (float*)d_out;

    cudaFuncSetAttribute(gemm1_kernel, cudaFuncAttributeMaxDynamicSharedMemorySize, SMEM_BYTES);
    cudaFuncSetAttribute(gemm2_kernel, cudaFuncAttributeMaxDynamicSharedMemorySize, SMEM_BYTES);

    cudaLaunchAttribute attr[1];
    attr[0].id = cudaLaunchAttributeProgrammaticStreamSerialization;
    attr[0].val.programmaticStreamSerializationAllowed = 1;

    setup_kernel<<<513, 256>>>(hs, ids, out);

    {   // gemm1: PDL secondary of setup (setup triggers at END -> race-free)
        cudaLaunchConfig_t cfg = {};
        cfg.gridDim = dim3(MAX_TILES, FDIM / 64, 1); cfg.blockDim = dim3(128, 1, 1);
        cfg.dynamicSmemBytes = SMEM_BYTES;
        cfg.attrs = attr; cfg.numAttrs = 1;
        cudaLaunchKernelEx(&cfg, gemm1_kernel, gw);
    }
    {   // gemm2: PDL secondary of gemm1 (gemm1 triggers at TOP -> launches
        // during gemm1's last wave; waits before touching d_act)
        cudaLaunchConfig_t cfg = {};
        cfg.gridDim = dim3(MAX_TILES, HDIM / 128, 1); cfg.blockDim = dim3(128, 1, 1);
        cfg.dynamicSmemBytes = SMEM_BYTES;
        cfg.attrs = attr; cfg.numAttrs = 1;
        cudaLaunchKernelEx(&cfg, gemm2_kernel, dw, tw, out);
    }
}